// round 17
// baseline (speedup 1.0000x reference)
#include <cuda_runtime.h>
#include <cuda_fp16.h>
#include <math.h>
#include <stdint.h>

// ---------------------------------------------------------------------------
// SimpleCNN (DCLS) forward, B=4096.
// R17: R14 (quad-ordered conv2 M, register-shuffle pool straight to gmem,
// 2-tap weight staging) with the staging ring restored to 3 buffers —
// 2-buffer rotation raced: stage(p+1) could overwrite pair p-1 mid-read.
// ---------------------------------------------------------------------------

#define B_MAX 4096

__device__ float g_K1[32 * 36];
__device__ float g_K2[64 * 32 * 36];
__device__ __half g_W1t[32 * 32];                // [oc][tap(25,pad32)] fp16
__device__ __half g_W2t[25 * 64 * 32];           // [tap][oc][ic] fp16
__device__ __half g_h2h[(size_t)B_MAX * 3136];   // conv2 out, fp16
__device__ __half g_F1h[128 * 3136];             // fc1 weights, fp16

__device__ __forceinline__ uint32_t smem_u32(const void* p) {
    uint32_t a;
    asm("{ .reg .u64 t; cvta.to.shared.u64 t, %1; cvt.u32.u64 %0, t; }" : "=r"(a) : "l"(p));
    return a;
}

__device__ __forceinline__ void ldmx4(uint32_t* r, uint32_t addr) {
    asm volatile("ldmatrix.sync.aligned.m8n8.x4.shared.b16 {%0,%1,%2,%3}, [%4];"
        : "=r"(r[0]), "=r"(r[1]), "=r"(r[2]), "=r"(r[3]) : "r"(addr));
}

__device__ __forceinline__ void mma16816(float* c, const uint32_t* a, const uint32_t* b) {
    asm volatile(
        "mma.sync.aligned.m16n8k16.row.col.f32.f16.f16.f32 "
        "{%0,%1,%2,%3}, {%4,%5,%6,%7}, {%8,%9}, {%0,%1,%2,%3};"
        : "+f"(c[0]), "+f"(c[1]), "+f"(c[2]), "+f"(c[3])
        : "r"(a[0]), "r"(a[1]), "r"(a[2]), "r"(a[3]), "r"(b[0]), "r"(b[1]));
}

__device__ __forceinline__ void cp_async16(uint32_t dst, const void* src) {
    asm volatile("cp.async.ca.shared.global [%0], [%1], 16;" :: "r"(dst), "l"(src));
}
#define CP_COMMIT() asm volatile("cp.async.commit_group;" ::: "memory")
#define CP_WAIT1()  asm volatile("cp.async.wait_group 1;" ::: "memory")
#define CP_WAIT0()  asm volatile("cp.async.wait_group 0;" ::: "memory")

__device__ __forceinline__ float rmax4(float v) {
    v = fmaxf(v, __shfl_xor_sync(0xFFFFFFFFu, v, 4));
    v = fmaxf(v, __shfl_xor_sync(0xFFFFFFFFu, v, 8));
    return v;
}

// ---------------- DCLS kernel construction ---------------------------------

__global__ void zero_k() {
    int i = blockIdx.x * blockDim.x + threadIdx.x;
    if (i < 32 * 36) g_K1[i] = 0.f;
    if (i < 64 * 32 * 36) g_K2[i] = 0.f;
}

__device__ __forceinline__ void dcls_scatter(float* grid, float w, float pa, float pb) {
    float p1c = fminf(fmaxf(pa, -2.f), 2.f) + 2.f;
    float p2c = fminf(fmaxf(pb, -2.f), 2.f) + 2.f;
    int i1 = (int)floorf(p1c);
    int i2 = (int)floorf(p2c);
    float r1 = p1c - (float)i1;
    float r2 = p2c - (float)i2;
    atomicAdd(&grid[i1 * 6 + i2],           w * (1.f - r1) * (1.f - r2));
    atomicAdd(&grid[(i1 + 1) * 6 + i2],     w * r1 * (1.f - r2));
    atomicAdd(&grid[i1 * 6 + i2 + 1],       w * (1.f - r1) * r2);
    atomicAdd(&grid[(i1 + 1) * 6 + i2 + 1], w * r1 * r2);
}

__global__ void build_k(const float* __restrict__ w1, const float* __restrict__ p1,
                        const float* __restrict__ w2, const float* __restrict__ p2) {
    int idx = blockIdx.x * blockDim.x + threadIdx.x;
    if (idx < 512) {
        float w = w1[idx];
        int f = idx / 16;
        dcls_scatter(g_K1 + f * 36, w, p1[idx], p1[512 + idx]);
    } else if (idx < 512 + 65536) {
        int e = idx - 512;
        float w = w2[e];
        int f = e / 32;
        dcls_scatter(g_K2 + f * 36, w, p2[e], p2[65536 + e]);
    }
}

__global__ void repack_all(const float* __restrict__ W) {
    int i = blockIdx.x * blockDim.x + threadIdx.x;
    if (i < 1024) {
        int oc = i >> 5, t = i & 31;
        float w = (t < 25) ? g_K1[oc * 36 + (t / 5) * 6 + (t % 5)] : 0.f;
        g_W1t[i] = __float2half(w);
    }
    if (i < 51200) {
        int t = i / 2048, r = i % 2048;
        int oc = r >> 5, ic = r & 31;
        float w = g_K2[(oc * 32 + ic) * 36 + (t / 5) * 6 + (t % 5)];
        g_W2t[i] = __float2half(w);
    }
    if (i < 128 * 3136) g_F1h[i] = __float2half(W[i]);
}

// ---------------- fused conv1 + pool + conv2 + pool ------------------------
// CTA = 1 image, 256 thr (8 warps = 4 m-quadrants x 2 n-halves).
// SMEM: Xpad@0 (2048) | W1@2048 (2560) | A 8x1280@4608 | X2@14848 (25920) |
//   W2 3 pair-buf@40768 (30720). Total 71488.

#define XP_OFF   0
#define W1_OFF   2048
#define A_OFF    4608
#define X2_OFF   14848
#define W2_OFF   40768
#define WROWB    80
#define WPAIR    10240                       // 2 taps x 64 rows x 80B
#define C2_SMEM  71488

__global__ __launch_bounds__(256, 2) void fused_conv(const float* __restrict__ x,
                                                     const float* __restrict__ b1,
                                                     const float* __restrict__ b2) {
    extern __shared__ __align__(16) char dsm[];
    __shared__ float sB1[32];
    __shared__ float sB2[64];
    uint32_t Su = smem_u32(dsm);

    int tid = threadIdx.x;
    int w = tid >> 5, l = tid & 31;
    int wm = w & 3, wn = w >> 2;
    int b = blockIdx.x;

    // zero Xpad..X2 (covers padding borders)
    for (int i = tid; i < W2_OFF / 16; i += 256)
        ((uint4*)dsm)[i] = make_uint4(0u, 0u, 0u, 0u);
    // stage tap pair 0 (taps 0,1) into buf 0
    {
#pragma unroll
        for (int i = 0; i < 2; i++) {
            int idx = tid + 256 * i;
            int r = idx >> 2, c = idx & 3;          // r: 0..127
            int t = r >> 6;                         // 0 or 1
            cp_async16(Su + W2_OFF + (uint32_t)(r * WROWB + c * 16),
                       (const char*)g_W2t + (t * 64 + (r & 63)) * 64 + c * 16);
        }
        CP_COMMIT();
    }
    if (tid < 32) sB1[tid] = b1[tid];
    if (tid < 64) sB2[tid] = b2[tid];
    __syncthreads();

    // fill Xpad fp16 and W1
    const float* xi = x + (size_t)b * 784;
    for (int i = tid; i < 784; i += 256) {
        int y = i / 28, c = i % 28;
        *((__half*)(dsm + XP_OFF) + (y + 2) * 32 + c + 2) = __float2half(xi[i]);
    }
    {
        const uint32_t* w1s = (const uint32_t*)g_W1t;     // 512 u32
        for (int i = tid; i < 512; i += 256) {
            int r = i >> 4, c = i & 15;
            *(uint32_t*)(dsm + W1_OFF + r * 80 + c * 4) = w1s[i];
        }
    }
    __syncthreads();

    // ---- conv1 phase: 49 m16 tiles (784 sites) spread over 8 warps ----
    {
        uint32_t AwB = (uint32_t)(A_OFF + w * 1280);
        uint32_t AwU = Su + AwB;
        const __half* XPh = (const __half*)(dsm + XP_OFF);

        for (int T = w; T < 49; T += 8) {
            for (int j = l; j < 80; j += 32) {
                int sl = j / 5, dy = j % 5;
                int sp = T * 16 + sl;
                int p = sp >> 2, sub = sp & 3;
                int y = 2 * (p / 14) + (sub >> 1);
                int xx = 2 * (p % 14) + (sub & 1);
                const __half* sr = XPh + (y + dy) * 32 + xx;
                __half* dr = (__half*)(dsm + AwB + sl * 80) + dy * 5;
                dr[0] = sr[0]; dr[1] = sr[1]; dr[2] = sr[2]; dr[3] = sr[3]; dr[4] = sr[4];
            }
            __syncwarp();
            uint32_t a0[4], a1[4];
            ldmx4(a0, AwU + (uint32_t)((l & 15) * 80 + (l >> 4) * 16));
            ldmx4(a1, AwU + (uint32_t)((l & 15) * 80 + 32 + (l >> 4) * 16));
            __syncwarp();

#pragma unroll
            for (int n = 0; n < 4; n++) {
                const char* wr = dsm + W1_OFF + (n * 8 + (l >> 2)) * 80 + (l & 3) * 4;
                uint32_t b0[2] = { *(const uint32_t*)wr, *(const uint32_t*)(wr + 16) };
                uint32_t b1f[2] = { *(const uint32_t*)(wr + 32), *(const uint32_t*)(wr + 48) };
                float acc[4] = {0.f, 0.f, 0.f, 0.f};
                mma16816(acc, a0, b0);
                mma16816(acc, a1, b1f);
                float c0 = rmax4(acc[0]), c1 = rmax4(acc[1]);
                float c2 = rmax4(acc[2]), c3 = rmax4(acc[3]);
                if ((l & 12) == 0) {
                    int oc0 = n * 8 + 2 * (l & 3);
                    float bb0 = sB1[oc0], bb1 = sB1[oc0 + 1];
                    int qa = 4 * T + (l >> 4);
                    int qb = qa + 2;
                    int ga = (qa / 14 + 2) * 18 + (qa % 14) + 2;
                    int gb = (qb / 14 + 2) * 18 + (qb % 14) + 2;
                    __half2 ha = __floats2half2_rn(fmaxf(c0 + bb0, 0.f), fmaxf(c1 + bb1, 0.f));
                    __half2 hb = __floats2half2_rn(fmaxf(c2 + bb0, 0.f), fmaxf(c3 + bb1, 0.f));
                    *(__half2*)(dsm + X2_OFF + ga * 80 + 2 * oc0) = ha;
                    *(__half2*)(dsm + X2_OFF + gb * 80 + 2 * oc0) = hb;
                }
            }
        }
    }
    __syncthreads();

    // ---- conv2 phase: quad-ordered sites s' = q*4 + sub ----
    uint32_t Xu = Su + X2_OFF;
    uint32_t Wu = Su + W2_OFF;

    uint32_t aBase[4];
#pragma unroll
    for (int mi = 0; mi < 4; mi++) {
        int ti = wm * 4 + mi;
        int sp = ti * 16 + (l & 15);
        int q = sp >> 2, sub = sp & 3;
        int y = 0, xx = 0;
        if (q < 49) {
            y = 2 * (q / 7) + (sub >> 1);
            xx = 2 * (q % 7) + (sub & 1);
        }
        // no +2 pad offset — the tap sweep (dy,dx 0..4) absorbs the padding
        aBase[mi] = Xu + (uint32_t)((y * 18 + xx) * 80) + (uint32_t)((l >> 4) * 16);
    }
    uint32_t bOff = (uint32_t)((wn * 32 + (l >> 2)) * WROWB + (l & 3) * 4);

    float acc[4][4][4];
#pragma unroll
    for (int mi = 0; mi < 4; mi++)
#pragma unroll
        for (int n = 0; n < 4; n++)
#pragma unroll
            for (int k = 0; k < 4; k++) acc[mi][n][k] = 0.f;

    int dy0 = 0, dx0 = 0;                    // tap counters
    for (int p = 0; p < 13; p++) {
        if (p < 12) {
            int tb = 2 * (p + 1);
            uint32_t wdst = Wu + (uint32_t)(((p + 1) % 3) * WPAIR);
#pragma unroll
            for (int i = 0; i < 2; i++) {
                int idx = tid + 256 * i;
                int r = idx >> 2, c = idx & 3;
                int t = tb + (r >> 6);
                if (t < 25)
                    cp_async16(wdst + (uint32_t)(r * WROWB + c * 16),
                               (const char*)g_W2t + (t * 64 + (r & 63)) * 64 + c * 16);
            }
            CP_COMMIT();
            CP_WAIT1();
        } else {
            CP_WAIT0();
        }
        __syncthreads();

        uint32_t wpb = Wu + (uint32_t)((p % 3) * WPAIR);
        int ntap = (p == 12) ? 1 : 2;
#pragma unroll
        for (int e = 0; e < 2; e++) {
            if (e >= ntap) break;
            uint32_t doff = (uint32_t)((dy0 * 18 + dx0) * 80);
            uint32_t wb = wpb + (uint32_t)(e * 5120);
            if (++dx0 == 5) { dx0 = 0; ++dy0; }

#pragma unroll
            for (int kc = 0; kc < 2; kc++) {
                uint32_t ah[4][4];
#pragma unroll
                for (int mi = 0; mi < 4; mi++)
                    ldmx4(ah[mi], aBase[mi] + doff + kc * 32);
                uint32_t bh_base = wb + bOff + (uint32_t)(kc * 32);
#pragma unroll
                for (int n = 0; n < 4; n++) {
                    uint32_t o = (uint32_t)n * (8 * WROWB);
                    uint32_t bh[2];
                    bh[0] = *(const uint32_t*)(dsm + (bh_base + o - Su));
                    bh[1] = *(const uint32_t*)(dsm + (bh_base + o + 16 - Su));
#pragma unroll
                    for (int mi = 0; mi < 4; mi++)
                        mma16816(acc[mi][n], ah[mi], bh);
                }
            }
        }
    }

    // ---- epilogue: pool via shuffles, bias+relu, store fp16 to g_h2h ----
    __half* h2b = g_h2h + (size_t)b * 3136;
#pragma unroll
    for (int mi = 0; mi < 4; mi++) {
        int ti = wm * 4 + mi;
#pragma unroll
        for (int n = 0; n < 4; n++) {
            float c0 = rmax4(acc[mi][n][0]);
            float c1 = rmax4(acc[mi][n][1]);
            float c2 = rmax4(acc[mi][n][2]);
            float c3 = rmax4(acc[mi][n][3]);
            if ((l & 12) == 0) {
                int oc0 = (wn * 4 + n) * 8 + 2 * (l & 3);
                float bb0 = sB2[oc0], bb1 = sB2[oc0 + 1];
                int q0 = ti * 4 + (l >> 4);
                int q2 = q0 + 2;
                if (q0 < 49) {
                    h2b[oc0 * 49 + q0]       = __float2half(fmaxf(c0 + bb0, 0.f));
                    h2b[(oc0 + 1) * 49 + q0] = __float2half(fmaxf(c1 + bb1, 0.f));
                }
                if (q2 < 49) {
                    h2b[oc0 * 49 + q2]       = __float2half(fmaxf(c2 + bb0, 0.f));
                    h2b[(oc0 + 1) * 49 + q2] = __float2half(fmaxf(c3 + bb1, 0.f));
                }
            }
        }
    }
}

// ---------------- FC1 (M=32, N=128, pure fp16) + fused FC2 -----------------

#define F1ROW  144
#define F1BUF  ((32 + 128) * F1ROW)          // 23040
#define FC1_SMEM (3 * F1BUF)                 // 69120

__global__ __launch_bounds__(256, 2) void fc1_fused(
        const float* __restrict__ bias, const float* __restrict__ W2,
        const float* __restrict__ b2f, float* __restrict__ out) {
    extern __shared__ __align__(16) char fsm[];
    __shared__ float sW2[1280];
    __shared__ float sB2[10];
    __shared__ float sBias[128];
    uint32_t Su = smem_u32(fsm);

    int tid = threadIdx.x;
    int w = tid >> 5, l = tid & 31;
    int wm = w >> 2, wn = w & 3;
    int m0 = blockIdx.x * 32;

    for (int i = tid; i < 1280; i += 256) sW2[i] = W2[i];
    if (tid < 10) sB2[tid] = b2f[tid];
    if (tid < 128) sBias[tid] = bias[tid];

    float acc[4][4];
#pragma unroll
    for (int nt = 0; nt < 4; nt++)
#pragma unroll
        for (int k = 0; k < 4; k++) acc[nt][k] = 0.f;

    auto stage = [&](int kt, int buf) {
        uint32_t dst0 = Su + (uint32_t)(buf * F1BUF);
        int k0 = kt * 64;
#pragma unroll
        for (int i = 0; i < 5; i++) {
            int j = tid + 256 * i;
            int rrow = j >> 3, c = j & 7;
            const __half* src = (rrow < 32)
                ? g_h2h + (size_t)(m0 + rrow) * 3136 + k0 + c * 8
                : g_F1h + (size_t)(rrow - 32) * 3136 + k0 + c * 8;
            cp_async16(dst0 + (uint32_t)(rrow * F1ROW + c * 16), src);
        }
        CP_COMMIT();
    };

    stage(0, 0);

    uint32_t aOff = (uint32_t)((wm * 16 + (l & 15)) * F1ROW + (l >> 4) * 16);
    uint32_t bRow = (uint32_t)(32 + wn * 32 + (l >> 2));
    uint32_t bW0 = (uint32_t)((l & 3) * 4);

    for (int kt = 0; kt < 49; kt++) {
        if (kt < 48) { stage(kt + 1, (kt + 1) % 3); CP_WAIT1(); }
        else CP_WAIT0();
        __syncthreads();
        uint32_t bufo = (uint32_t)((kt % 3) * F1BUF);

#pragma unroll
        for (int kc = 0; kc < 4; kc++) {
            uint32_t ah[4];
            ldmx4(ah, Su + bufo + aOff + kc * 32);
#pragma unroll
            for (int nt = 0; nt < 4; nt++) {
                uint32_t rb = bufo + (bRow + nt * 8) * F1ROW + bW0 + kc * 32;
                uint32_t bh[2];
                bh[0] = *(const uint32_t*)(fsm + rb);
                bh[1] = *(const uint32_t*)(fsm + rb + 16);
                mma16816(acc[nt], ah, bh);
            }
        }
        __syncthreads();
    }

    float* hP = (float*)fsm;                 // [32][132]
    int r0 = wm * 16 + (l >> 2);
#pragma unroll
    for (int nt = 0; nt < 4; nt++) {
        int col = wn * 32 + nt * 8 + 2 * (l & 3);
        float bs0 = sBias[col], bs1 = sBias[col + 1];
        hP[r0 * 132 + col]       = fmaxf(acc[nt][0] + bs0, 0.f);
        hP[r0 * 132 + col + 1]   = fmaxf(acc[nt][1] + bs1, 0.f);
        hP[(r0 + 8) * 132 + col]     = fmaxf(acc[nt][2] + bs0, 0.f);
        hP[(r0 + 8) * 132 + col + 1] = fmaxf(acc[nt][3] + bs1, 0.f);
    }
    __syncthreads();

    for (int it = tid; it < 320; it += 256) {
        int r = it / 10, o = it % 10;
        const float* hr = hP + r * 132;
        const float* wr = sW2 + o * 128;
        float s = 0.f;
#pragma unroll
        for (int c = 0; c < 128; c++) s += hr[c] * wr[c];
        out[(size_t)(m0 + r) * 10 + o] = s + sB2[o];
    }
}

// ---------------------------------------------------------------------------

extern "C" void kernel_launch(void* const* d_in, const int* in_sizes, int n_in,
                              void* d_out, int out_size) {
    const float* x    = (const float*)d_in[0];
    const float* w1   = (const float*)d_in[1];
    const float* p1   = (const float*)d_in[2];
    const float* b1   = (const float*)d_in[3];
    const float* w2   = (const float*)d_in[4];
    const float* p2   = (const float*)d_in[5];
    const float* b2   = (const float*)d_in[6];
    const float* fc1w = (const float*)d_in[7];
    const float* fc1b = (const float*)d_in[8];
    const float* fc2w = (const float*)d_in[9];
    const float* fc2b = (const float*)d_in[10];
    float* out = (float*)d_out;

    int B = in_sizes[0] / 784;
    if (B > B_MAX) B = B_MAX;

    zero_k<<<(64 * 32 * 36 + 255) / 256, 256>>>();
    build_k<<<(512 + 65536 + 255) / 256, 256>>>(w1, p1, w2, p2);
    repack_all<<<(128 * 3136 + 255) / 256, 256>>>(fc1w);

    cudaFuncSetAttribute(fused_conv, cudaFuncAttributeMaxDynamicSharedMemorySize, C2_SMEM);
    fused_conv<<<B, 256, C2_SMEM>>>(x, b1, b2);

    cudaFuncSetAttribute(fc1_fused, cudaFuncAttributeMaxDynamicSharedMemorySize, FC1_SMEM);
    fc1_fused<<<B / 32, 256, FC1_SMEM>>>(fc1b, fc2w, fc2b, out);
}